// round 6
// baseline (speedup 1.0000x reference)
#include <cuda_runtime.h>
#include <math.h>

#define BB 64      // batch
#define TT 512     // decode steps
#define TE 1024    // encoder steps
#define EE 512     // encoder dim
#define UU 256     // units
#define NC 64      // classes
#define GG 1024    // 4*U gates
#define VV 1024    // U (x) + E (ctx) + U (h)

// ---------------- scratch (static device globals; no allocation) -------------
__device__ float d_secrets[BB * TT * UU];
__device__ float d_enc1[BB * TE * UU];
__device__ float d_enc2[BB * TE * UU];
__device__ float d_o1[BB * TT * UU];
__device__ float d_o2[BB * TT * UU];
__device__ float d_m1o[BB * TT * UU];
__device__ float d_m2o[BB * TT * UU];
__device__ float d_lg[BB * TT * NC];
__device__ float d_vT[2 * VV * BB];      // [layer][row 0..1023][batch]  (transposed v)
__device__ float d_Z[2 * BB * GG];       // [layer][batch][gate]
__device__ unsigned d_bar[128];          // grid-barrier flags (monotone)

__device__ __forceinline__ float tanh_fast(float x) {
    float y;
    asm("tanh.approx.f32 %0, %1;" : "=f"(y) : "f"(x));
    return y;
}

// -------- grid barrier: release/acquire flags, monotone phase ---------------
__device__ __forceinline__ void gbar(unsigned& ph) {
    __threadfence();
    __syncthreads();
    ph++;
    if (threadIdx.x == 0) {
        asm volatile("st.release.gpu.global.u32 [%0], %1;"
                     :: "l"(&d_bar[blockIdx.x]), "r"(ph) : "memory");
    }
    if (threadIdx.x < 128) {
        unsigned v;
        do {
            asm volatile("ld.acquire.gpu.global.u32 %0, [%1];"
                         : "=r"(v) : "l"(&d_bar[threadIdx.x]) : "memory");
        } while ((int)(v - ph) < 0);
    }
    __syncthreads();
    __threadfence();
}

// ---------------------------------------------------------------------------
// Persistent decoder: both attention-LSTM layers, pipelined (layer2 one step
// behind layer1). grid = 128 CTAs (L = bid/64, b = bid%64), block = 512.
// ---------------------------------------------------------------------------
__global__ __launch_bounds__(512, 1) void decoder_persistent(
    const float* __restrict__ speech,
    const float* __restrict__ Wa1W, const float* __restrict__ Wa1b,
    const float* __restrict__ va1W, const float* __restrict__ va1b,
    const float* __restrict__ K1, const float* __restrict__ R1, const float* __restrict__ b1,
    const float* __restrict__ Wa2W, const float* __restrict__ Wa2b,
    const float* __restrict__ va2W, const float* __restrict__ va2b,
    const float* __restrict__ K2, const float* __restrict__ R2, const float* __restrict__ b2)
{
    const int bid = blockIdx.x;
    const int tid = threadIdx.x;
    const int L = bid >> 6;         // 0 = layer1, 1 = layer2
    const int b = bid & 63;
    const int lane = tid & 31, warp = tid >> 5;

    const float* enc = L ? d_enc2 : d_enc1;
    const float* WaW = L ? Wa2W : Wa1W;
    const float* Wab = L ? Wa2b : Wa1b;
    const float* vaW = L ? va2W : va1W;
    const float* vab = L ? va2b : va1b;
    const float* Kw  = L ? K2 : K1;
    const float* Rw  = L ? R2 : R1;
    const float* bz  = L ? b2 : b1;
    float* outbuf = L ? d_o2 : d_o1;
    float* vT = d_vT + L * (VV * BB);
    float* Zl = d_Z + L * (BB * GG);

    __shared__ float sh_h[UU];
    __shared__ float sh_s[UU];
    __shared__ __align__(16) float sh_dyn[64 * 68 + 64 * 20];  // 22.5 KB union
    float* sh_l = sh_dyn;          // [1024] logits / probs
    float* red  = sh_dyn + 1024;   // [2048] reductions / ctx partials

    float c_reg = 0.0f;            // cell state (threads 0..255)
    unsigned ph = *((volatile unsigned*)&d_bar[bid]);   // same start value grid-wide

    for (int k = 0; k <= 513; k++) {
        const int t = k - L;                    // this layer's step
        const bool attnAct = (t >= 0) && (t < TT);
        const bool gateAct = (t >= 1) && (t <= TT);

        if (k) gbar(ph);   // B0: Z of previous iteration complete

        // ---------------- phase A: gates -> h_{t-1} ------------------------
        if (tid < UU) {
            if (gateAct) {
                const float* Zb = Zl + b * GG;
                float zi = bz[tid]       + __ldcg(Zb + tid);
                float zf = bz[tid + 256] + __ldcg(Zb + tid + 256);
                float zg = bz[tid + 512] + __ldcg(Zb + tid + 512);
                float zo = bz[tid + 768] + __ldcg(Zb + tid + 768);
                float ig = 1.0f / (1.0f + expf(-zi));
                float fg = 1.0f / (1.0f + expf(-zf));
                float og = 1.0f / (1.0f + expf(-zo));
                c_reg = fg * c_reg + ig * tanhf(zg);
                float h = og * tanhf(c_reg);
                sh_h[tid] = h;
                __stcg(vT + (768 + tid) * BB + b, h);
                __stcg(outbuf + ((size_t)b * TT + (t - 1)) * UU + tid, h);
            } else if (attnAct) {   // t == 0 init
                c_reg = 0.0f;
                sh_h[tid] = 0.0f;
                __stcg(vT + (768 + tid) * BB + b, 0.0f);
            }
        }

        gbar(ph);          // B1: h / o1 rows visible grid-wide

        // ---------------- phase B: attention for step t --------------------
        if (attnAct) {
            // x_t  (layer2: norm of layer1's h_t, written this iteration)
            float xv = 0.0f;
            if (tid < UU) {
                xv = (L == 0) ? d_secrets[((size_t)b * TT + t) * UU + tid]
                              : __ldcg(d_o1 + ((size_t)b * TT + t) * UU + tid);
            }
            if (L == 1) {   // uniform per CTA -> syncthreads legal
                red[tid]       = (tid < UU) ? xv : 0.0f;
                red[512 + tid] = (tid < UU) ? xv * xv : 0.0f;
                __syncthreads();
                for (int o = 256; o > 0; o >>= 1) {
                    if (tid < o) {
                        red[tid] += red[tid + o];
                        red[512 + tid] += red[512 + tid + o];
                    }
                    __syncthreads();
                }
                const float mean = red[0] * (1.0f / 256.0f);
                const float var  = red[512] * (1.0f / 256.0f) - mean * mean;
                const float sc = rsqrtf(var + 1e-4f);
                xv = (xv - mean) * sc;
                __syncthreads();
            }
            if (tid < UU) __stcg(vT + tid * BB + b, xv);

            // s = h @ Wa + Wa_b
            {
                const int uu = tid & 255, half = tid >> 8;
                float acc = 0.0f;
                const float* wp = WaW + (size_t)(half * 128) * UU + uu;
#pragma unroll 4
                for (int kk = 0; kk < 128; kk++)
                    acc += sh_h[half * 128 + kk] * wp[(size_t)kk * UU];
                red[tid] = acc;
                __syncthreads();
                if (tid < UU) sh_s[tid] = red[tid] + red[tid + 256] + Wab[tid];
                __syncthreads();
            }

            // logits[te] = va . tanh(s + enc[b,te,:]) + va_b
            {
                float va_r[8], s_r[8];
#pragma unroll
                for (int j = 0; j < 4; j++) {
                    va_r[j]     = vaW[lane * 4 + j];
                    s_r[j]      = sh_s[lane * 4 + j];
                    va_r[4 + j] = vaW[128 + lane * 4 + j];
                    s_r[4 + j]  = sh_s[128 + lane * 4 + j];
                }
                const float vb = vab[0];
#pragma unroll 2
                for (int te = warp; te < TE; te += 16) {
                    const float4* ep =
                        reinterpret_cast<const float4*>(enc + ((size_t)b * TE + te) * UU);
                    float4 ea = ep[lane];
                    float4 eb = ep[32 + lane];
                    float acc;
                    acc  = va_r[0] * tanh_fast(s_r[0] + ea.x);
                    acc += va_r[1] * tanh_fast(s_r[1] + ea.y);
                    acc += va_r[2] * tanh_fast(s_r[2] + ea.z);
                    acc += va_r[3] * tanh_fast(s_r[3] + ea.w);
                    acc += va_r[4] * tanh_fast(s_r[4] + eb.x);
                    acc += va_r[5] * tanh_fast(s_r[5] + eb.y);
                    acc += va_r[6] * tanh_fast(s_r[6] + eb.z);
                    acc += va_r[7] * tanh_fast(s_r[7] + eb.w);
#pragma unroll
                    for (int o = 16; o; o >>= 1)
                        acc += __shfl_xor_sync(0xffffffffu, acc, o);
                    if (lane == 0) sh_l[te] = acc + vb;
                }
            }
            __syncthreads();

            // softmax over Te (keep unnormalized p + invS)
            float invS;
            {
                float l0 = sh_l[tid], l1 = sh_l[tid + 512];
                red[tid] = fmaxf(l0, l1);
                __syncthreads();
                for (int o = 256; o > 0; o >>= 1) {
                    if (tid < o) red[tid] = fmaxf(red[tid], red[tid + o]);
                    __syncthreads();
                }
                const float M = red[0];
                __syncthreads();
                float p0 = __expf(l0 - M), p1 = __expf(l1 - M);
                sh_l[tid] = p0;
                sh_l[tid + 512] = p1;
                red[tid] = p0 + p1;
                __syncthreads();
                for (int o = 256; o > 0; o >>= 1) {
                    if (tid < o) red[tid] += red[tid + o];
                    __syncthreads();
                }
                invS = 1.0f / red[0];
                __syncthreads();
            }

            // ctx = (sum_te p_te * speech[b,te,:]) * invS -> vT rows 256..767
            {
                const int e4 = tid & 127, grp = tid >> 7;
                const float4* sp =
                    reinterpret_cast<const float4*>(speech + (size_t)b * TE * EE) + e4;
                float4 acc = make_float4(0.f, 0.f, 0.f, 0.f);
                for (int te = grp; te < TE; te += 4) {
                    const float w = sh_l[te];
                    float4 s4 = sp[(size_t)te * 128];
                    acc.x += w * s4.x; acc.y += w * s4.y;
                    acc.z += w * s4.z; acc.w += w * s4.w;
                }
                reinterpret_cast<float4*>(red)[grp * 128 + e4] = acc;
                __syncthreads();
                if (grp == 0) {
                    float4* pr = reinterpret_cast<float4*>(red);
                    float4 a = pr[e4], b2_ = pr[128 + e4], c2 = pr[256 + e4], d2 = pr[384 + e4];
                    const int ce = 256 + e4 * 4;
                    __stcg(vT + (ce + 0) * BB + b, (a.x + b2_.x + c2.x + d2.x) * invS);
                    __stcg(vT + (ce + 1) * BB + b, (a.y + b2_.y + c2.y + d2.y) * invS);
                    __stcg(vT + (ce + 2) * BB + b, (a.z + b2_.z + c2.z + d2.z) * invS);
                    __stcg(vT + (ce + 3) * BB + b, (a.w + b2_.w + c2.w + d2.w) * invS);
                }
            }
        }

        gbar(ph);          // B2: v (all batches, this layer) visible

        // ---------------- phase D: Z[:, 16 cols] = v @ [K;R] ----------------
        if (attnAct) {
            float (*vsh)[68] = reinterpret_cast<float(*)[68]>(sh_dyn);
            float (*wsh)[20] = reinterpret_cast<float(*)[20]>(sh_dyn + 64 * 68);
            const int c0 = b * 16;
            const int rg = tid & 7, cg = (tid >> 3) & 3, bg = tid >> 5;
            float acc[4][4] = {};

            for (int tile = 0; tile < 16; tile++) {
                const int rbase = tile * 64;
#pragma unroll
                for (int i = 0; i < 2; i++) {
                    const int e4i = i * 512 + tid;
                    const int r = e4i >> 4, b4 = e4i & 15;
                    float4 vv = __ldcg(
                        reinterpret_cast<const float4*>(vT + (size_t)(rbase + r) * BB) + b4);
                    *reinterpret_cast<float4*>(&vsh[r][b4 * 4]) = vv;
                }
                if (tid < 256) {
                    const int r = tid >> 2, c4 = tid & 3;
                    const int gr = rbase + r;
                    const float* Wrow = (gr < 768) ? (Kw + (size_t)gr * GG)
                                                   : (Rw + (size_t)(gr - 768) * GG);
                    *reinterpret_cast<float4*>(&wsh[r][c4 * 4]) =
                        *reinterpret_cast<const float4*>(Wrow + c0 + c4 * 4);
                }
                __syncthreads();
#pragma unroll
                for (int rr = 0; rr < 8; rr++) {
                    const int r = rr * 8 + rg;
                    float4 vv = *reinterpret_cast<const float4*>(&vsh[r][bg * 4]);
                    float4 ww = *reinterpret_cast<const float4*>(&wsh[r][cg * 4]);
                    const float vvv[4] = {vv.x, vv.y, vv.z, vv.w};
                    const float www[4] = {ww.x, ww.y, ww.z, ww.w};
#pragma unroll
                    for (int i = 0; i < 4; i++)
#pragma unroll
                        for (int j = 0; j < 4; j++)
                            acc[i][j] += vvv[i] * www[j];
                }
                __syncthreads();
            }
            // reduce over rg (lane bits 0..2)
#pragma unroll
            for (int i = 0; i < 4; i++)
#pragma unroll
                for (int j = 0; j < 4; j++) {
                    float a = acc[i][j];
                    a += __shfl_xor_sync(0xffffffffu, a, 1);
                    a += __shfl_xor_sync(0xffffffffu, a, 2);
                    a += __shfl_xor_sync(0xffffffffu, a, 4);
                    acc[i][j] = a;
                }
            if (rg == 0) {
#pragma unroll
                for (int i = 0; i < 4; i++)
#pragma unroll
                    for (int j = 0; j < 4; j++)
                        __stcg(Zl + (size_t)(bg * 4 + i) * GG + c0 + cg * 4 + j, acc[i][j]);
            }
        }
    }
}

// ---------------------------------------------------------------------------
// Generic tiled SGEMM: C[M,N] = A[M,K] @ B[K,N] + bias[N]  (one-time + head)
// ---------------------------------------------------------------------------
__global__ __launch_bounds__(128) void gemm_kernel(
    const float* __restrict__ A, const float* __restrict__ Bm,
    const float* __restrict__ bias, float* __restrict__ C,
    int M, int K, int N)
{
    __shared__ __align__(16) float As[16][68];
    __shared__ __align__(16) float Bs[16][64];
    const int m0 = blockIdx.x * 64;
    const int n0 = blockIdx.y * 64;
    const int tid = threadIdx.x;
    const int tx = tid & 15, ty = tid >> 4;

    float acc[8][4] = {};

    for (int k0 = 0; k0 < K; k0 += 16) {
#pragma unroll
        for (int i = 0; i < 8; i++) {
            const int e = i * 128 + tid;
            const int m = e >> 4, kk = e & 15;
            As[kk][m] = A[(size_t)(m0 + m) * K + k0 + kk];
        }
#pragma unroll
        for (int i = 0; i < 8; i++) {
            const int e = i * 128 + tid;
            const int kk = e >> 6, nn = e & 63;
            Bs[kk][nn] = Bm[(size_t)(k0 + kk) * N + n0 + nn];
        }
        __syncthreads();
#pragma unroll
        for (int kk = 0; kk < 16; kk++) {
            float4 b4  = *reinterpret_cast<const float4*>(&Bs[kk][tx * 4]);
            float4 alo = *reinterpret_cast<const float4*>(&As[kk][ty * 8]);
            float4 ahi = *reinterpret_cast<const float4*>(&As[kk][ty * 8 + 4]);
            const float a[8] = {alo.x, alo.y, alo.z, alo.w, ahi.x, ahi.y, ahi.z, ahi.w};
            const float bb[4] = {b4.x, b4.y, b4.z, b4.w};
#pragma unroll
            for (int q = 0; q < 8; q++)
#pragma unroll
                for (int j = 0; j < 4; j++)
                    acc[q][j] += a[q] * bb[j];
        }
        __syncthreads();
    }
#pragma unroll
    for (int q = 0; q < 8; q++) {
        const int m = m0 + ty * 8 + q;
#pragma unroll
        for (int j = 0; j < 4; j++) {
            const int n = n0 + tx * 4 + j;
            C[(size_t)m * N + n] = acc[q][j] + bias[n];
        }
    }
}

// whatever_norm over last dim (256), in-place. grid = rows, block = 256.
__global__ __launch_bounds__(256) void norm_kernel(float* __restrict__ x)
{
    __shared__ float rs[256], rq[256];
    const int row = blockIdx.x, tid = threadIdx.x;
    const float v = x[(size_t)row * UU + tid];
    rs[tid] = v;
    rq[tid] = v * v;
    __syncthreads();
    for (int o = 128; o > 0; o >>= 1) {
        if (tid < o) { rs[tid] += rs[tid + o]; rq[tid] += rq[tid + o]; }
        __syncthreads();
    }
    const float mean = rs[0] * (1.0f / 256.0f);
    const float var = rq[0] * (1.0f / 256.0f) - mean * mean;
    const float sc = rsqrtf(var + 1e-4f);
    x[(size_t)row * UU + tid] = (v - mean) * sc;
}

// Row softmax over NC=64. block = 256 (8 warps -> 8 rows), grid = rows/8.
__global__ __launch_bounds__(256) void softmax_kernel(
    const float* __restrict__ in, float* __restrict__ outp)
{
    const int warp = threadIdx.x >> 5, lane = threadIdx.x & 31;
    const int row = blockIdx.x * 8 + warp;
    const float* p = in + (size_t)row * NC;
    float a = p[lane], b = p[lane + 32];
    float m = fmaxf(a, b);
#pragma unroll
    for (int o = 16; o; o >>= 1) m = fmaxf(m, __shfl_xor_sync(0xffffffffu, m, o));
    const float ea = expf(a - m), eb = expf(b - m);
    float s = ea + eb;
#pragma unroll
    for (int o = 16; o; o >>= 1) s += __shfl_xor_sync(0xffffffffu, s, o);
    const float inv = 1.0f / s;
    outp[(size_t)row * NC + lane] = ea * inv;
    outp[(size_t)row * NC + lane + 32] = eb * inv;
}

// ---------------------------------------------------------------------------
extern "C" void kernel_launch(void* const* d_in, const int* in_sizes, int n_in,
                              void* d_out, int out_size)
{
    const float* trans  = (const float*)d_in[0];
    const float* speech = (const float*)d_in[1];
    const float* embW   = (const float*)d_in[2];
    const float* embb   = (const float*)d_in[3];
    const float* Ua1W = (const float*)d_in[4];
    const float* Ua1b = (const float*)d_in[5];
    const float* Wa1W = (const float*)d_in[6];
    const float* Wa1b = (const float*)d_in[7];
    const float* va1W = (const float*)d_in[8];
    const float* va1b = (const float*)d_in[9];
    const float* K1   = (const float*)d_in[10];
    const float* R1   = (const float*)d_in[11];
    const float* b1   = (const float*)d_in[12];
    const float* Ua2W = (const float*)d_in[13];
    const float* Ua2b = (const float*)d_in[14];
    const float* Wa2W = (const float*)d_in[15];
    const float* Wa2b = (const float*)d_in[16];
    const float* va2W = (const float*)d_in[17];
    const float* va2b = (const float*)d_in[18];
    const float* K2   = (const float*)d_in[19];
    const float* R2   = (const float*)d_in[20];
    const float* b2   = (const float*)d_in[21];
    const float* m1W  = (const float*)d_in[22];
    const float* m1b  = (const float*)d_in[23];
    const float* m2W  = (const float*)d_in[24];
    const float* m2b  = (const float*)d_in[25];
    const float* dW   = (const float*)d_in[26];
    const float* db   = (const float*)d_in[27];

    float *secrets, *enc1, *enc2, *o2, *m1o, *m2o, *lg;
    cudaGetSymbolAddress((void**)&secrets, d_secrets);
    cudaGetSymbolAddress((void**)&enc1, d_enc1);
    cudaGetSymbolAddress((void**)&enc2, d_enc2);
    cudaGetSymbolAddress((void**)&o2, d_o2);
    cudaGetSymbolAddress((void**)&m1o, d_m1o);
    cudaGetSymbolAddress((void**)&m2o, d_m2o);
    cudaGetSymbolAddress((void**)&lg, d_lg);

    const int ROWS = BB * TT;      // 32768
    const int EROWS = BB * TE;     // 65536

    // One-time projections
    gemm_kernel<<<dim3(ROWS / 64, UU / 64), 128>>>(trans, embW, embb, secrets, ROWS, NC, UU);
    gemm_kernel<<<dim3(EROWS / 64, UU / 64), 128>>>(speech, Ua1W, Ua1b, enc1, EROWS, EE, UU);
    gemm_kernel<<<dim3(EROWS / 64, UU / 64), 128>>>(speech, Ua2W, Ua2b, enc2, EROWS, EE, UU);

    // Both recurrent layers, pipelined, in ONE persistent kernel
    decoder_persistent<<<128, 512>>>(speech,
        Wa1W, Wa1b, va1W, va1b, K1, R1, b1,
        Wa2W, Wa2b, va2W, va2b, K2, R2, b2);

    // MLP head
    norm_kernel<<<ROWS, 256>>>(o2);
    gemm_kernel<<<dim3(ROWS / 64, UU / 64), 128>>>(o2, m1W, m1b, m1o, ROWS, UU, UU);
    norm_kernel<<<ROWS, 256>>>(m1o);
    gemm_kernel<<<dim3(ROWS / 64, UU / 64), 128>>>(m1o, m2W, m2b, m2o, ROWS, UU, UU);
    norm_kernel<<<ROWS, 256>>>(m2o);
    gemm_kernel<<<dim3(ROWS / 64, NC / 64), 128>>>(m2o, dW, db, lg, ROWS, UU, NC);
    softmax_kernel<<<ROWS / 8, 256>>>(lg, (float*)d_out);

    (void)in_sizes; (void)n_in; (void)out_size;
}

// round 8
// speedup vs baseline: 1.0972x; 1.0972x over previous
#include <cuda_runtime.h>
#include <cuda_fp16.h>
#include <math.h>

#define BB 64      // batch
#define TT 512     // decode steps
#define TE 1024    // encoder steps
#define EE 512     // encoder dim
#define UU 256     // units
#define NC 64      // classes
#define GG 1024    // 4*U gates
#define VV 1024    // U (x) + E (ctx) + U (h)

// ---------------- scratch (static device globals; no allocation) -------------
__device__ float d_secrets[BB * TT * UU];
__device__ __half d_enc1h[BB * TE * UU];   // fp16 enc, layer1
__device__ __half d_enc2h[BB * TE * UU];   // fp16 enc, layer2
__device__ __half d_speechh[BB * TE * EE]; // fp16 speech
__device__ float d_o1[BB * TT * UU];
__device__ float d_o2[BB * TT * UU];
__device__ float d_m1o[BB * TT * UU];
__device__ float d_m2o[BB * TT * UU];
__device__ float d_lg[BB * TT * NC];
__device__ float d_vT[2 * VV * BB];      // [layer][row 0..1023][batch]  (transposed v)
__device__ float d_Z[2 * BB * GG];       // [layer][batch][gate]
__device__ unsigned d_bar[128];          // grid-barrier flags (monotone)

__device__ __forceinline__ float tanh_fast(float x) {
    float y;
    asm("tanh.approx.f32 %0, %1;" : "=f"(y) : "f"(x));
    return y;
}

// -------- grid barrier: release/acquire flags, monotone phase ---------------
__device__ __forceinline__ void gbar(unsigned& ph) {
    __threadfence();
    __syncthreads();
    ph++;
    if (threadIdx.x == 0) {
        asm volatile("st.release.gpu.global.u32 [%0], %1;"
                     :: "l"(&d_bar[blockIdx.x]), "r"(ph) : "memory");
    }
    if (threadIdx.x < 128) {
        unsigned v;
        do {
            asm volatile("ld.acquire.gpu.global.u32 %0, [%1];"
                         : "=r"(v) : "l"(&d_bar[threadIdx.x]) : "memory");
        } while ((int)(v - ph) < 0);
    }
    __syncthreads();
    __threadfence();
}

// ---------------------------------------------------------------------------
// Persistent decoder: both attention-LSTM layers, pipelined (layer2 one step
// behind layer1). grid = 128 CTAs (L = bid/64, b = bid%64), block = 512.
// ---------------------------------------------------------------------------
__global__ __launch_bounds__(512, 1) void decoder_persistent(
    const float* __restrict__ Wa1W, const float* __restrict__ Wa1b,
    const float* __restrict__ va1W, const float* __restrict__ va1b,
    const float* __restrict__ K1, const float* __restrict__ R1, const float* __restrict__ b1,
    const float* __restrict__ Wa2W, const float* __restrict__ Wa2b,
    const float* __restrict__ va2W, const float* __restrict__ va2b,
    const float* __restrict__ K2, const float* __restrict__ R2, const float* __restrict__ b2)
{
    const int bid = blockIdx.x;
    const int tid = threadIdx.x;
    const int L = bid >> 6;         // 0 = layer1, 1 = layer2
    const int b = bid & 63;
    const int lane = tid & 31, warp = tid >> 5;

    const __half* ench = L ? d_enc2h : d_enc1h;
    const float* WaW = L ? Wa2W : Wa1W;
    const float* Wab = L ? Wa2b : Wa1b;
    const float* vaW = L ? va2W : va1W;
    const float* vab = L ? va2b : va1b;
    const float* Kw  = L ? K2 : K1;
    const float* Rw  = L ? R2 : R1;
    const float* bz  = L ? b2 : b1;
    float* outbuf = L ? d_o2 : d_o1;
    float* vT = d_vT + L * (VV * BB);
    float* Zl = d_Z + L * (BB * GG);

    __shared__ float sh_h[UU];
    __shared__ float sh_s[UU];
    __shared__ __align__(16) float sh_dyn[64 * 68 + 64 * 20];  // 22.5 KB union
    float* sh_l = sh_dyn;          // [1024] logits / probs
    float* red  = sh_dyn + 1024;   // reductions / ctx partials (4096 floats OK)

    float c_reg = 0.0f;            // cell state (threads 0..255)
    unsigned ph = *((volatile unsigned*)&d_bar[bid]);   // same start value grid-wide

    for (int k = 0; k <= 513; k++) {
        const int t = k - L;                    // this layer's step
        const bool attnAct = (t >= 0) && (t < TT);
        const bool gateAct = (t >= 1) && (t <= TT);

        if (k) gbar(ph);   // B0: Z of previous iteration complete

        // ---------------- phase A: gates -> h_{t-1} ------------------------
        if (tid < UU) {
            if (gateAct) {
                const float* Zb = Zl + b * GG;
                float zi = bz[tid]       + __ldcg(Zb + tid);
                float zf = bz[tid + 256] + __ldcg(Zb + tid + 256);
                float zg = bz[tid + 512] + __ldcg(Zb + tid + 512);
                float zo = bz[tid + 768] + __ldcg(Zb + tid + 768);
                float ig = 1.0f / (1.0f + expf(-zi));
                float fg = 1.0f / (1.0f + expf(-zf));
                float og = 1.0f / (1.0f + expf(-zo));
                c_reg = fg * c_reg + ig * tanhf(zg);
                float h = og * tanhf(c_reg);
                sh_h[tid] = h;
                __stcg(vT + (768 + tid) * BB + b, h);
                __stcg(outbuf + ((size_t)b * TT + (t - 1)) * UU + tid, h);
            } else if (attnAct) {   // t == 0 init
                c_reg = 0.0f;
                sh_h[tid] = 0.0f;
                __stcg(vT + (768 + tid) * BB + b, 0.0f);
            }
        }

        gbar(ph);          // B1: h / o1 rows visible grid-wide

        // ---------------- phase B: attention for step t --------------------
        if (attnAct) {
            // x_t  (layer2: norm of layer1's h_t, written this iteration)
            float xv = 0.0f;
            if (tid < UU) {
                xv = (L == 0) ? d_secrets[((size_t)b * TT + t) * UU + tid]
                              : __ldcg(d_o1 + ((size_t)b * TT + t) * UU + tid);
            }
            if (L == 1) {   // uniform per CTA -> syncthreads legal
                red[tid]       = (tid < UU) ? xv : 0.0f;
                red[512 + tid] = (tid < UU) ? xv * xv : 0.0f;
                __syncthreads();
                for (int o = 256; o > 0; o >>= 1) {
                    if (tid < o) {
                        red[tid] += red[tid + o];
                        red[512 + tid] += red[512 + tid + o];
                    }
                    __syncthreads();
                }
                const float mean = red[0] * (1.0f / 256.0f);
                const float var  = red[512] * (1.0f / 256.0f) - mean * mean;
                const float sc = rsqrtf(var + 1e-4f);
                xv = (xv - mean) * sc;
                __syncthreads();
            }
            if (tid < UU) __stcg(vT + tid * BB + b, xv);

            // s = h @ Wa + Wa_b
            {
                const int uu = tid & 255, half = tid >> 8;
                float acc = 0.0f;
                const float* wp = WaW + (size_t)(half * 128) * UU + uu;
#pragma unroll 4
                for (int kk = 0; kk < 128; kk++)
                    acc += sh_h[half * 128 + kk] * wp[(size_t)kk * UU];
                red[tid] = acc;
                __syncthreads();
                if (tid < UU) sh_s[tid] = red[tid] + red[tid + 256] + Wab[tid];
                __syncthreads();
            }

            // logits[te] = va . tanh(s + enc[b,te,:]) + va_b  (fp16 enc)
            {
                float va_r[8], s_r[8];
#pragma unroll
                for (int j = 0; j < 8; j++) {
                    va_r[j] = vaW[lane * 8 + j];
                    s_r[j]  = sh_s[lane * 8 + j];
                }
                const float vb = vab[0];
                const uint4* ebase =
                    reinterpret_cast<const uint4*>(ench + (size_t)b * TE * UU);
                for (int te = warp; te < TE; te += 32) {
                    uint4 qa = ebase[(size_t)te * 32 + lane];
                    uint4 qb = ebase[(size_t)(te + 16) * 32 + lane];
                    float a0 = 0.0f, a1 = 0.0f;
                    {
                        const __half2* h2 = reinterpret_cast<const __half2*>(&qa);
#pragma unroll
                        for (int p = 0; p < 4; p++) {
                            float2 f = __half22float2(h2[p]);
                            a0 += va_r[2 * p]     * tanh_fast(s_r[2 * p]     + f.x);
                            a0 += va_r[2 * p + 1] * tanh_fast(s_r[2 * p + 1] + f.y);
                        }
                    }
                    {
                        const __half2* h2 = reinterpret_cast<const __half2*>(&qb);
#pragma unroll
                        for (int p = 0; p < 4; p++) {
                            float2 f = __half22float2(h2[p]);
                            a1 += va_r[2 * p]     * tanh_fast(s_r[2 * p]     + f.x);
                            a1 += va_r[2 * p + 1] * tanh_fast(s_r[2 * p + 1] + f.y);
                        }
                    }
#pragma unroll
                    for (int o = 16; o; o >>= 1) {
                        a0 += __shfl_xor_sync(0xffffffffu, a0, o);
                        a1 += __shfl_xor_sync(0xffffffffu, a1, o);
                    }
                    if (lane == 0) {
                        sh_l[te] = a0 + vb;
                        sh_l[te + 16] = a1 + vb;
                    }
                }
            }
            __syncthreads();

            // softmax over Te (keep unnormalized p + invS)
            float invS;
            {
                float l0 = sh_l[tid], l1 = sh_l[tid + 512];
                red[tid] = fmaxf(l0, l1);
                __syncthreads();
                for (int o = 256; o > 0; o >>= 1) {
                    if (tid < o) red[tid] = fmaxf(red[tid], red[tid + o]);
                    __syncthreads();
                }
                const float M = red[0];
                __syncthreads();
                float p0 = __expf(l0 - M), p1 = __expf(l1 - M);
                sh_l[tid] = p0;
                sh_l[tid + 512] = p1;
                red[tid] = p0 + p1;
                __syncthreads();
                for (int o = 256; o > 0; o >>= 1) {
                    if (tid < o) red[tid] += red[tid + o];
                    __syncthreads();
                }
                invS = 1.0f / red[0];
                __syncthreads();
            }

            // ctx = (sum_te p_te * speech[b,te,:]) * invS  (fp16 speech)
            {
                const int e8 = tid & 63;       // uint4 index (8 fp16) in row
                const int grp = tid >> 6;      // 8 te-groups
                const uint4* sp =
                    reinterpret_cast<const uint4*>(d_speechh + (size_t)b * TE * EE) + e8;
                float acc[8] = {0.f, 0.f, 0.f, 0.f, 0.f, 0.f, 0.f, 0.f};
                for (int te = grp; te < TE; te += 16) {
                    const float w0 = sh_l[te];
                    const float w1 = sh_l[te + 8];
                    uint4 q0 = sp[(size_t)te * 64];
                    uint4 q1 = sp[(size_t)(te + 8) * 64];
                    const __half2* h0 = reinterpret_cast<const __half2*>(&q0);
                    const __half2* h1 = reinterpret_cast<const __half2*>(&q1);
#pragma unroll
                    for (int p = 0; p < 4; p++) {
                        float2 f0 = __half22float2(h0[p]);
                        float2 f1 = __half22float2(h1[p]);
                        acc[2 * p]     += w0 * f0.x + w1 * f1.x;
                        acc[2 * p + 1] += w0 * f0.y + w1 * f1.y;
                    }
                }
#pragma unroll
                for (int j = 0; j < 8; j++)
                    red[grp * 512 + e8 * 8 + j] = acc[j];
                __syncthreads();
                float s = 0.0f;
#pragma unroll
                for (int g = 0; g < 8; g++)
                    s += red[g * 512 + tid];
                __stcg(vT + (256 + tid) * BB + b, s * invS);
            }
        }

        gbar(ph);          // B2: v (all batches, this layer) visible

        // ---------------- phase D: Z[:, 16 cols] = v @ [K;R] ----------------
        if (attnAct) {
            float (*vsh)[68] = reinterpret_cast<float(*)[68]>(sh_dyn);
            float (*wsh)[20] = reinterpret_cast<float(*)[20]>(sh_dyn + 64 * 68);
            const int c0 = b * 16;
            const int rg = tid & 7, cg = (tid >> 3) & 3, bg = tid >> 5;
            float acc[4][4] = {};

            for (int tile = 0; tile < 16; tile++) {
                const int rbase = tile * 64;
#pragma unroll
                for (int i = 0; i < 2; i++) {
                    const int e4i = i * 512 + tid;
                    const int r = e4i >> 4, b4 = e4i & 15;
                    float4 vv = __ldcg(
                        reinterpret_cast<const float4*>(vT + (size_t)(rbase + r) * BB) + b4);
                    *reinterpret_cast<float4*>(&vsh[r][b4 * 4]) = vv;
                }
                if (tid < 256) {
                    const int r = tid >> 2, c4 = tid & 3;
                    const int gr = rbase + r;
                    const float* Wrow = (gr < 768) ? (Kw + (size_t)gr * GG)
                                                   : (Rw + (size_t)(gr - 768) * GG);
                    *reinterpret_cast<float4*>(&wsh[r][c4 * 4]) =
                        *reinterpret_cast<const float4*>(Wrow + c0 + c4 * 4);
                }
                __syncthreads();
#pragma unroll
                for (int rr = 0; rr < 8; rr++) {
                    const int r = rr * 8 + rg;
                    float4 vv = *reinterpret_cast<const float4*>(&vsh[r][bg * 4]);
                    float4 ww = *reinterpret_cast<const float4*>(&wsh[r][cg * 4]);
                    const float vvv[4] = {vv.x, vv.y, vv.z, vv.w};
                    const float www[4] = {ww.x, ww.y, ww.z, ww.w};
#pragma unroll
                    for (int i = 0; i < 4; i++)
#pragma unroll
                        for (int j = 0; j < 4; j++)
                            acc[i][j] += vvv[i] * www[j];
                }
                __syncthreads();
            }
            // reduce over rg (lane bits 0..2)
#pragma unroll
            for (int i = 0; i < 4; i++)
#pragma unroll
                for (int j = 0; j < 4; j++) {
                    float a = acc[i][j];
                    a += __shfl_xor_sync(0xffffffffu, a, 1);
                    a += __shfl_xor_sync(0xffffffffu, a, 2);
                    a += __shfl_xor_sync(0xffffffffu, a, 4);
                    acc[i][j] = a;
                }
            if (rg == 0) {
#pragma unroll
                for (int i = 0; i < 4; i++)
#pragma unroll
                    for (int j = 0; j < 4; j++)
                        __stcg(Zl + (size_t)(bg * 4 + i) * GG + c0 + cg * 4 + j, acc[i][j]);
            }
        }
    }
}

// ---------------------------------------------------------------------------
// fp32 -> fp16 bulk convert, 8 elems/thread.
// ---------------------------------------------------------------------------
__global__ __launch_bounds__(256) void f2h_kernel(
    const float* __restrict__ in, __half* __restrict__ out, int n8)
{
    const int i = blockIdx.x * blockDim.x + threadIdx.x;
    if (i >= n8) return;
    const float4* p = reinterpret_cast<const float4*>(in) + 2 * i;
    float4 a = p[0], c = p[1];
    __half2 h0 = __floats2half2_rn(a.x, a.y);
    __half2 h1 = __floats2half2_rn(a.z, a.w);
    __half2 h2 = __floats2half2_rn(c.x, c.y);
    __half2 h3 = __floats2half2_rn(c.z, c.w);
    uint4 q;
    q.x = *reinterpret_cast<unsigned*>(&h0);
    q.y = *reinterpret_cast<unsigned*>(&h1);
    q.z = *reinterpret_cast<unsigned*>(&h2);
    q.w = *reinterpret_cast<unsigned*>(&h3);
    reinterpret_cast<uint4*>(out)[i] = q;
}

// ---------------------------------------------------------------------------
// Generic tiled SGEMM: C[M,N] = A[M,K] @ B[K,N] + bias[N], OutT in {float,half}
// ---------------------------------------------------------------------------
__device__ __forceinline__ void store_out(float* p, float v) { *p = v; }
__device__ __forceinline__ void store_out(__half* p, float v) {
    *p = __float2half_rn(v);
}

template <typename OutT>
__global__ __launch_bounds__(128) void gemm_kernel(
    const float* __restrict__ A, const float* __restrict__ Bm,
    const float* __restrict__ bias, OutT* __restrict__ C,
    int M, int K, int N)
{
    __shared__ __align__(16) float As[16][68];
    __shared__ __align__(16) float Bs[16][64];
    const int m0 = blockIdx.x * 64;
    const int n0 = blockIdx.y * 64;
    const int tid = threadIdx.x;
    const int tx = tid & 15, ty = tid >> 4;

    float acc[8][4] = {};

    for (int k0 = 0; k0 < K; k0 += 16) {
#pragma unroll
        for (int i = 0; i < 8; i++) {
            const int e = i * 128 + tid;
            const int m = e >> 4, kk = e & 15;
            As[kk][m] = A[(size_t)(m0 + m) * K + k0 + kk];
        }
#pragma unroll
        for (int i = 0; i < 8; i++) {
            const int e = i * 128 + tid;
            const int kk = e >> 6, nn = e & 63;
            Bs[kk][nn] = Bm[(size_t)(k0 + kk) * N + n0 + nn];
        }
        __syncthreads();
#pragma unroll
        for (int kk = 0; kk < 16; kk++) {
            float4 b4  = *reinterpret_cast<const float4*>(&Bs[kk][tx * 4]);
            float4 alo = *reinterpret_cast<const float4*>(&As[kk][ty * 8]);
            float4 ahi = *reinterpret_cast<const float4*>(&As[kk][ty * 8 + 4]);
            const float a[8] = {alo.x, alo.y, alo.z, alo.w, ahi.x, ahi.y, ahi.z, ahi.w};
            const float bb[4] = {b4.x, b4.y, b4.z, b4.w};
#pragma unroll
            for (int q = 0; q < 8; q++)
#pragma unroll
                for (int j = 0; j < 4; j++)
                    acc[q][j] += a[q] * bb[j];
        }
        __syncthreads();
    }
#pragma unroll
    for (int q = 0; q < 8; q++) {
        const int m = m0 + ty * 8 + q;
#pragma unroll
        for (int j = 0; j < 4; j++) {
            const int n = n0 + tx * 4 + j;
            store_out(&C[(size_t)m * N + n], acc[q][j] + bias[n]);
        }
    }
}

// whatever_norm over last dim (256), in-place. grid = rows, block = 256.
__global__ __launch_bounds__(256) void norm_kernel(float* __restrict__ x)
{
    __shared__ float rs[256], rq[256];
    const int row = blockIdx.x, tid = threadIdx.x;
    const float v = x[(size_t)row * UU + tid];
    rs[tid] = v;
    rq[tid] = v * v;
    __syncthreads();
    for (int o = 128; o > 0; o >>= 1) {
        if (tid < o) { rs[tid] += rs[tid + o]; rq[tid] += rq[tid + o]; }
        __syncthreads();
    }
    const float mean = rs[0] * (1.0f / 256.0f);
    const float var = rq[0] * (1.0f / 256.0f) - mean * mean;
    const float sc = rsqrtf(var + 1e-4f);
    x[(size_t)row * UU + tid] = (v - mean) * sc;
}

// Row softmax over NC=64. block = 256 (8 warps -> 8 rows), grid = rows/8.
__global__ __launch_bounds__(256) void softmax_kernel(
    const float* __restrict__ in, float* __restrict__ outp)
{
    const int warp = threadIdx.x >> 5, lane = threadIdx.x & 31;
    const int row = blockIdx.x * 8 + warp;
    const float* p = in + (size_t)row * NC;
    float a = p[lane], b = p[lane + 32];
    float m = fmaxf(a, b);
#pragma unroll
    for (int o = 16; o; o >>= 1) m = fmaxf(m, __shfl_xor_sync(0xffffffffu, m, o));
    const float ea = expf(a - m), eb = expf(b - m);
    float s = ea + eb;
#pragma unroll
    for (int o = 16; o; o >>= 1) s += __shfl_xor_sync(0xffffffffu, s, o);
    const float inv = 1.0f / s;
    outp[(size_t)row * NC + lane] = ea * inv;
    outp[(size_t)row * NC + lane + 32] = eb * inv;
}

// ---------------------------------------------------------------------------
extern "C" void kernel_launch(void* const* d_in, const int* in_sizes, int n_in,
                              void* d_out, int out_size)
{
    const float* trans  = (const float*)d_in[0];
    const float* speech = (const float*)d_in[1];
    const float* embW   = (const float*)d_in[2];
    const float* embb   = (const float*)d_in[3];
    const float* Ua1W = (const float*)d_in[4];
    const float* Ua1b = (const float*)d_in[5];
    const float* Wa1W = (const float*)d_in[6];
    const float* Wa1b = (const float*)d_in[7];
    const float* va1W = (const float*)d_in[8];
    const float* va1b = (const float*)d_in[9];
    const float* K1   = (const float*)d_in[10];
    const float* R1   = (const float*)d_in[11];
    const float* b1   = (const float*)d_in[12];
    const float* Ua2W = (const float*)d_in[13];
    const float* Ua2b = (const float*)d_in[14];
    const float* Wa2W = (const float*)d_in[15];
    const float* Wa2b = (const float*)d_in[16];
    const float* va2W = (const float*)d_in[17];
    const float* va2b = (const float*)d_in[18];
    const float* K2   = (const float*)d_in[19];
    const float* R2   = (const float*)d_in[20];
    const float* b2   = (const float*)d_in[21];
    const float* m1W  = (const float*)d_in[22];
    const float* m1b  = (const float*)d_in[23];
    const float* m2W  = (const float*)d_in[24];
    const float* m2b  = (const float*)d_in[25];
    const float* dW   = (const float*)d_in[26];
    const float* db   = (const float*)d_in[27];

    float *secrets, *o2, *m1o, *m2o, *lg;
    __half *enc1h, *enc2h, *speechh;
    cudaGetSymbolAddress((void**)&secrets, d_secrets);
    cudaGetSymbolAddress((void**)&enc1h, d_enc1h);
    cudaGetSymbolAddress((void**)&enc2h, d_enc2h);
    cudaGetSymbolAddress((void**)&speechh, d_speechh);
    cudaGetSymbolAddress((void**)&o2, d_o2);
    cudaGetSymbolAddress((void**)&m1o, d_m1o);
    cudaGetSymbolAddress((void**)&m2o, d_m2o);
    cudaGetSymbolAddress((void**)&lg, d_lg);

    const int ROWS = BB * TT;      // 32768
    const int EROWS = BB * TE;     // 65536

    // One-time projections (enc written directly as fp16) + speech conversion
    gemm_kernel<<<dim3(ROWS / 64, UU / 64), 128>>>(trans, embW, embb, secrets, ROWS, NC, UU);
    gemm_kernel<<<dim3(EROWS / 64, UU / 64), 128>>>(speech, Ua1W, Ua1b, enc1h, EROWS, EE, UU);
    gemm_kernel<<<dim3(EROWS / 64, UU / 64), 128>>>(speech, Ua2W, Ua2b, enc2h, EROWS, EE, UU);
    {
        const int n8 = BB * TE * EE / 8;
        f2h_kernel<<<(n8 + 255) / 256, 256>>>(speech, speechh, n8);
    }

    // Both recurrent layers, pipelined, in ONE persistent kernel
    decoder_persistent<<<128, 512>>>(
        Wa1W, Wa1b, va1W, va1b, K1, R1, b1,
        Wa2W, Wa2b, va2W, va2b, K2, R2, b2);

    // MLP head
    norm_kernel<<<ROWS, 256>>>(o2);
    gemm_kernel<<<dim3(ROWS / 64, UU / 64), 128>>>(o2, m1W, m1b, m1o, ROWS, UU, UU);
    norm_kernel<<<ROWS, 256>>>(m1o);
    gemm_kernel<<<dim3(ROWS / 64, UU / 64), 128>>>(m1o, m2W, m2b, m2o, ROWS, UU, UU);
    norm_kernel<<<ROWS, 256>>>(m2o);
    gemm_kernel<<<dim3(ROWS / 64, NC / 64), 128>>>(m2o, dW, db, lg, ROWS, UU, NC);
    softmax_kernel<<<ROWS / 8, 256>>>(lg, (float*)d_out);

    (void)in_sizes; (void)n_in; (void)out_size;
}

// round 10
// speedup vs baseline: 1.2847x; 1.1709x over previous
#include <cuda_runtime.h>
#include <cuda_fp16.h>
#include <math.h>

#define BB 64      // batch
#define TT 512     // decode steps
#define TE 1024    // encoder steps
#define EE 512     // encoder dim
#define UU 256     // units
#define NC 64      // classes
#define GG 1024    // 4*U gates
#define VV 1024    // U (x) + E (ctx) + U (h)

// ---------------- scratch (static device globals; no allocation) -------------
__device__ float d_secrets[BB * TT * UU];
__device__ __half d_enc1h[BB * TE * UU];   // fp16 enc, layer1
__device__ __half d_enc2h[BB * TE * UU];   // fp16 enc, layer2
__device__ __half d_speechh[BB * TE * EE]; // fp16 speech
__device__ float d_o1[BB * TT * UU];
__device__ float d_o2[BB * TT * UU];
__device__ float d_m1o[BB * TT * UU];
__device__ float d_m2o[BB * TT * UU];
__device__ float d_lg[BB * TT * NC];
__device__ float d_vT[2 * VV * BB];      // [layer][row 0..1023][batch]  (transposed v)
__device__ float d_Z[2 * BB * GG];       // [layer][batch][gate]
__device__ unsigned d_bar[128];          // grid-barrier flags (monotone)

__device__ __forceinline__ float tanh_fast(float x) {
    float y;
    asm("tanh.approx.f32 %0, %1;" : "=f"(y) : "f"(x));
    return y;
}

// -------- grid barrier: release/acquire flags, monotone phase ---------------
__device__ __forceinline__ void gbar(unsigned& ph) {
    __threadfence();
    __syncthreads();
    ph++;
    if (threadIdx.x == 0) {
        asm volatile("st.release.gpu.global.u32 [%0], %1;"
                     :: "l"(&d_bar[blockIdx.x]), "r"(ph) : "memory");
    }
    if (threadIdx.x < 128) {
        unsigned v;
        do {
            asm volatile("ld.acquire.gpu.global.u32 %0, [%1];"
                         : "=r"(v) : "l"(&d_bar[threadIdx.x]) : "memory");
        } while ((int)(v - ph) < 0);
    }
    __syncthreads();
    __threadfence();
}

// ---------------------------------------------------------------------------
// Persistent decoder: both attention-LSTM layers, pipelined (layer2 one step
// behind layer1). grid = 128 CTAs (L = bid/64, b = bid%64), block = 512.
// ---------------------------------------------------------------------------
__global__ __launch_bounds__(512, 1) void decoder_persistent(
    const float* __restrict__ Wa1W, const float* __restrict__ Wa1b,
    const float* __restrict__ va1W, const float* __restrict__ va1b,
    const float* __restrict__ K1, const float* __restrict__ R1, const float* __restrict__ b1,
    const float* __restrict__ Wa2W, const float* __restrict__ Wa2b,
    const float* __restrict__ va2W, const float* __restrict__ va2b,
    const float* __restrict__ K2, const float* __restrict__ R2, const float* __restrict__ b2)
{
    const int bid = blockIdx.x;
    const int tid = threadIdx.x;
    const int L = bid >> 6;         // 0 = layer1, 1 = layer2
    const int b = bid & 63;
    const int lane = tid & 31, warp = tid >> 5;

    const __half* ench = L ? d_enc2h : d_enc1h;
    const float* WaW = L ? Wa2W : Wa1W;
    const float* Wab = L ? Wa2b : Wa1b;
    const float* vaW = L ? va2W : va1W;
    const float* vab = L ? va2b : va1b;
    const float* Kw  = L ? K2 : K1;
    const float* Rw  = L ? R2 : R1;
    const float* bz  = L ? b2 : b1;
    float* outbuf = L ? d_o2 : d_o1;
    float* vT = d_vT + L * (VV * BB);
    float* Zl = d_Z + L * (BB * GG);

    __shared__ float sh_h[UU];
    __shared__ float sh_s[UU];
    __shared__ __align__(16) float sh_dyn[64 * 68 + 64 * 20];  // 22.5 KB union
    float* sh_l = sh_dyn;          // [1024] logits / probs
    float* red  = sh_dyn + 1024;   // reductions / ctx partials (4096 floats OK)

    float c_reg = 0.0f;            // cell state (threads 0..255)
    unsigned ph = *((volatile unsigned*)&d_bar[bid]);   // same start value grid-wide

    for (int k = 0; k <= 513; k++) {
        const int t = k - L;                    // this layer's step
        const bool attnAct = (t >= 0) && (t < TT);
        const bool gateAct = (t >= 1) && (t <= TT);

        if (k) gbar(ph);   // B0: Z of previous iteration complete

        // ---------------- phase A: gates -> h_{t-1} ------------------------
        if (tid < UU) {
            if (gateAct) {
                const float* Zb = Zl + b * GG;
                float zi = bz[tid]       + __ldcg(Zb + tid);
                float zf = bz[tid + 256] + __ldcg(Zb + tid + 256);
                float zg = bz[tid + 512] + __ldcg(Zb + tid + 512);
                float zo = bz[tid + 768] + __ldcg(Zb + tid + 768);
                float ig = 1.0f / (1.0f + expf(-zi));
                float fg = 1.0f / (1.0f + expf(-zf));
                float og = 1.0f / (1.0f + expf(-zo));
                c_reg = fg * c_reg + ig * tanhf(zg);
                float h = og * tanhf(c_reg);
                sh_h[tid] = h;
                __stcg(vT + (768 + tid) * BB + b, h);
                __stcg(outbuf + ((size_t)b * TT + (t - 1)) * UU + tid, h);
            } else if (attnAct) {   // t == 0 init
                c_reg = 0.0f;
                sh_h[tid] = 0.0f;
                __stcg(vT + (768 + tid) * BB + b, 0.0f);
            }
        }

        gbar(ph);          // B1: h / o1 rows visible grid-wide

        // ---------------- phase B: attention for step t --------------------
        if (attnAct) {
            // x_t  (layer2: norm of layer1's h_t, written this iteration)
            float xv = 0.0f;
            if (tid < UU) {
                xv = (L == 0) ? d_secrets[((size_t)b * TT + t) * UU + tid]
                              : __ldcg(d_o1 + ((size_t)b * TT + t) * UU + tid);
            }
            if (L == 1) {   // uniform per CTA -> syncthreads legal
                red[tid]       = (tid < UU) ? xv : 0.0f;
                red[512 + tid] = (tid < UU) ? xv * xv : 0.0f;
                __syncthreads();
                for (int o = 256; o > 0; o >>= 1) {
                    if (tid < o) {
                        red[tid] += red[tid + o];
                        red[512 + tid] += red[512 + tid + o];
                    }
                    __syncthreads();
                }
                const float mean = red[0] * (1.0f / 256.0f);
                const float var  = red[512] * (1.0f / 256.0f) - mean * mean;
                const float sc = rsqrtf(var + 1e-4f);
                xv = (xv - mean) * sc;
                __syncthreads();
            }
            if (tid < UU) __stcg(vT + tid * BB + b, xv);

            // s = h @ Wa + Wa_b
            {
                const int uu = tid & 255, half = tid >> 8;
                float acc = 0.0f;
                const float* wp = WaW + (size_t)(half * 128) * UU + uu;
#pragma unroll 8
                for (int kk = 0; kk < 128; kk++)
                    acc += sh_h[half * 128 + kk] * wp[(size_t)kk * UU];
                red[tid] = acc;
                __syncthreads();
                if (tid < UU) sh_s[tid] = red[tid] + red[tid + 256] + Wab[tid];
                __syncthreads();
            }

            // logits[te] = va . tanh(s + enc[b,te,:]) + va_b  (fp16 enc)
            // 4 rows in flight per warp-iteration (MLP=4)
            {
                float va_r[8], s_r[8];
#pragma unroll
                for (int j = 0; j < 8; j++) {
                    va_r[j] = vaW[lane * 8 + j];
                    s_r[j]  = sh_s[lane * 8 + j];
                }
                const float vb = vab[0];
                const uint4* ebase =
                    reinterpret_cast<const uint4*>(ench + (size_t)b * TE * UU);
#pragma unroll 1
                for (int te = warp; te < TE; te += 64) {
                    uint4 q0 = ebase[(size_t)(te)      * 32 + lane];
                    uint4 q1 = ebase[(size_t)(te + 16) * 32 + lane];
                    uint4 q2 = ebase[(size_t)(te + 32) * 32 + lane];
                    uint4 q3 = ebase[(size_t)(te + 48) * 32 + lane];
                    float a0 = 0.f, a1 = 0.f, a2 = 0.f, a3 = 0.f;
                    const __half2* h0 = reinterpret_cast<const __half2*>(&q0);
                    const __half2* h1 = reinterpret_cast<const __half2*>(&q1);
                    const __half2* h2 = reinterpret_cast<const __half2*>(&q2);
                    const __half2* h3 = reinterpret_cast<const __half2*>(&q3);
#pragma unroll
                    for (int p = 0; p < 4; p++) {
                        float2 f0 = __half22float2(h0[p]);
                        float2 f1 = __half22float2(h1[p]);
                        float2 f2 = __half22float2(h2[p]);
                        float2 f3 = __half22float2(h3[p]);
                        a0 += va_r[2 * p]     * tanh_fast(s_r[2 * p]     + f0.x);
                        a1 += va_r[2 * p]     * tanh_fast(s_r[2 * p]     + f1.x);
                        a2 += va_r[2 * p]     * tanh_fast(s_r[2 * p]     + f2.x);
                        a3 += va_r[2 * p]     * tanh_fast(s_r[2 * p]     + f3.x);
                        a0 += va_r[2 * p + 1] * tanh_fast(s_r[2 * p + 1] + f0.y);
                        a1 += va_r[2 * p + 1] * tanh_fast(s_r[2 * p + 1] + f1.y);
                        a2 += va_r[2 * p + 1] * tanh_fast(s_r[2 * p + 1] + f2.y);
                        a3 += va_r[2 * p + 1] * tanh_fast(s_r[2 * p + 1] + f3.y);
                    }
#pragma unroll
                    for (int o = 16; o; o >>= 1) {
                        a0 += __shfl_xor_sync(0xffffffffu, a0, o);
                        a1 += __shfl_xor_sync(0xffffffffu, a1, o);
                        a2 += __shfl_xor_sync(0xffffffffu, a2, o);
                        a3 += __shfl_xor_sync(0xffffffffu, a3, o);
                    }
                    if (lane == 0) {
                        sh_l[te]      = a0 + vb;
                        sh_l[te + 16] = a1 + vb;
                        sh_l[te + 32] = a2 + vb;
                        sh_l[te + 48] = a3 + vb;
                    }
                }
            }
            __syncthreads();

            // softmax over Te (keep unnormalized p + invS)
            float invS;
            {
                float l0 = sh_l[tid], l1 = sh_l[tid + 512];
                red[tid] = fmaxf(l0, l1);
                __syncthreads();
                for (int o = 256; o > 0; o >>= 1) {
                    if (tid < o) red[tid] = fmaxf(red[tid], red[tid + o]);
                    __syncthreads();
                }
                const float M = red[0];
                __syncthreads();
                float p0 = __expf(l0 - M), p1 = __expf(l1 - M);
                sh_l[tid] = p0;
                sh_l[tid + 512] = p1;
                red[tid] = p0 + p1;
                __syncthreads();
                for (int o = 256; o > 0; o >>= 1) {
                    if (tid < o) red[tid] += red[tid + o];
                    __syncthreads();
                }
                invS = 1.0f / red[0];
                __syncthreads();
            }

            // ctx = (sum_te p_te * speech[b,te,:]) * invS  (fp16 speech, MLP=4)
            {
                const int e8 = tid & 63;       // uint4 index (8 fp16) in row
                const int grp = tid >> 6;      // 8 te-groups
                const uint4* sp =
                    reinterpret_cast<const uint4*>(d_speechh + (size_t)b * TE * EE) + e8;
                float acc[8] = {0.f, 0.f, 0.f, 0.f, 0.f, 0.f, 0.f, 0.f};
#pragma unroll 1
                for (int te = grp; te < TE; te += 32) {
                    const float w0 = sh_l[te];
                    const float w1 = sh_l[te + 8];
                    const float w2 = sh_l[te + 16];
                    const float w3 = sh_l[te + 24];
                    uint4 q0 = sp[(size_t)(te)      * 64];
                    uint4 q1 = sp[(size_t)(te + 8)  * 64];
                    uint4 q2 = sp[(size_t)(te + 16) * 64];
                    uint4 q3 = sp[(size_t)(te + 24) * 64];
                    const __half2* h0 = reinterpret_cast<const __half2*>(&q0);
                    const __half2* h1 = reinterpret_cast<const __half2*>(&q1);
                    const __half2* h2 = reinterpret_cast<const __half2*>(&q2);
                    const __half2* h3 = reinterpret_cast<const __half2*>(&q3);
#pragma unroll
                    for (int p = 0; p < 4; p++) {
                        float2 f0 = __half22float2(h0[p]);
                        float2 f1 = __half22float2(h1[p]);
                        float2 f2 = __half22float2(h2[p]);
                        float2 f3 = __half22float2(h3[p]);
                        acc[2 * p]     += w0 * f0.x + w1 * f1.x + w2 * f2.x + w3 * f3.x;
                        acc[2 * p + 1] += w0 * f0.y + w1 * f1.y + w2 * f2.y + w3 * f3.y;
                    }
                }
#pragma unroll
                for (int j = 0; j < 8; j++)
                    red[grp * 512 + e8 * 8 + j] = acc[j];
                __syncthreads();
                float s = 0.0f;
#pragma unroll
                for (int g = 0; g < 8; g++)
                    s += red[g * 512 + tid];
                __stcg(vT + (256 + tid) * BB + b, s * invS);
            }
        }

        gbar(ph);          // B2: v (all batches, this layer) visible

        // ---------------- phase D: Z[:, 16 cols] = v @ [K;R] ----------------
        if (attnAct) {
            float (*vsh)[68] = reinterpret_cast<float(*)[68]>(sh_dyn);
            float (*wsh)[20] = reinterpret_cast<float(*)[20]>(sh_dyn + 64 * 68);
            const int c0 = b * 16;
            const int rg = tid & 7, cg = (tid >> 3) & 3, bg = tid >> 5;
            float acc[4][4] = {};

            for (int tile = 0; tile < 16; tile++) {
                const int rbase = tile * 64;
#pragma unroll
                for (int i = 0; i < 2; i++) {
                    const int e4i = i * 512 + tid;
                    const int r = e4i >> 4, b4 = e4i & 15;
                    float4 vv = __ldcg(
                        reinterpret_cast<const float4*>(vT + (size_t)(rbase + r) * BB) + b4);
                    *reinterpret_cast<float4*>(&vsh[r][b4 * 4]) = vv;
                }
                if (tid < 256) {
                    const int r = tid >> 2, c4 = tid & 3;
                    const int gr = rbase + r;
                    const float* Wrow = (gr < 768) ? (Kw + (size_t)gr * GG)
                                                   : (Rw + (size_t)(gr - 768) * GG);
                    *reinterpret_cast<float4*>(&wsh[r][c4 * 4]) =
                        *reinterpret_cast<const float4*>(Wrow + c0 + c4 * 4);
                }
                __syncthreads();
#pragma unroll
                for (int rr = 0; rr < 8; rr++) {
                    const int r = rr * 8 + rg;
                    float4 vv = *reinterpret_cast<const float4*>(&vsh[r][bg * 4]);
                    float4 ww = *reinterpret_cast<const float4*>(&wsh[r][cg * 4]);
                    const float vvv[4] = {vv.x, vv.y, vv.z, vv.w};
                    const float www[4] = {ww.x, ww.y, ww.z, ww.w};
#pragma unroll
                    for (int i = 0; i < 4; i++)
#pragma unroll
                        for (int j = 0; j < 4; j++)
                            acc[i][j] += vvv[i] * www[j];
                }
                __syncthreads();
            }
            // reduce over rg (lane bits 0..2)
#pragma unroll
            for (int i = 0; i < 4; i++)
#pragma unroll
                for (int j = 0; j < 4; j++) {
                    float a = acc[i][j];
                    a += __shfl_xor_sync(0xffffffffu, a, 1);
                    a += __shfl_xor_sync(0xffffffffu, a, 2);
                    a += __shfl_xor_sync(0xffffffffu, a, 4);
                    acc[i][j] = a;
                }
            if (rg == 0) {
#pragma unroll
                for (int i = 0; i < 4; i++)
#pragma unroll
                    for (int j = 0; j < 4; j++)
                        __stcg(Zl + (size_t)(bg * 4 + i) * GG + c0 + cg * 4 + j, acc[i][j]);
            }
        }
    }
}

// ---------------------------------------------------------------------------
// fp32 -> fp16 bulk convert, 8 elems/thread.
// ---------------------------------------------------------------------------
__global__ __launch_bounds__(256) void f2h_kernel(
    const float* __restrict__ in, __half* __restrict__ out, int n8)
{
    const int i = blockIdx.x * blockDim.x + threadIdx.x;
    if (i >= n8) return;
    const float4* p = reinterpret_cast<const float4*>(in) + 2 * i;
    float4 a = p[0], c = p[1];
    __half2 h0 = __floats2half2_rn(a.x, a.y);
    __half2 h1 = __floats2half2_rn(a.z, a.w);
    __half2 h2 = __floats2half2_rn(c.x, c.y);
    __half2 h3 = __floats2half2_rn(c.z, c.w);
    uint4 q;
    q.x = *reinterpret_cast<unsigned*>(&h0);
    q.y = *reinterpret_cast<unsigned*>(&h1);
    q.z = *reinterpret_cast<unsigned*>(&h2);
    q.w = *reinterpret_cast<unsigned*>(&h3);
    reinterpret_cast<uint4*>(out)[i] = q;
}

// ---------------------------------------------------------------------------
// Generic tiled SGEMM: C[M,N] = A[M,K] @ B[K,N] + bias[N], OutT in {float,half}
// ---------------------------------------------------------------------------
__device__ __forceinline__ void store_out(float* p, float v) { *p = v; }
__device__ __forceinline__ void store_out(__half* p, float v) {
    *p = __float2half_rn(v);
}

template <typename OutT>
__global__ __launch_bounds__(128) void gemm_kernel(
    const float* __restrict__ A, const float* __restrict__ Bm,
    const float* __restrict__ bias, OutT* __restrict__ C,
    int M, int K, int N)
{
    __shared__ __align__(16) float As[16][68];
    __shared__ __align__(16) float Bs[16][64];
    const int m0 = blockIdx.x * 64;
    const int n0 = blockIdx.y * 64;
    const int tid = threadIdx.x;
    const int tx = tid & 15, ty = tid >> 4;

    float acc[8][4] = {};

    for (int k0 = 0; k0 < K; k0 += 16) {
#pragma unroll
        for (int i = 0; i < 8; i++) {
            const int e = i * 128 + tid;
            const int m = e >> 4, kk = e & 15;
            As[kk][m] = A[(size_t)(m0 + m) * K + k0 + kk];
        }
#pragma unroll
        for (int i = 0; i < 8; i++) {
            const int e = i * 128 + tid;
            const int kk = e >> 6, nn = e & 63;
            Bs[kk][nn] = Bm[(size_t)(k0 + kk) * N + n0 + nn];
        }
        __syncthreads();
#pragma unroll
        for (int kk = 0; kk < 16; kk++) {
            float4 b4  = *reinterpret_cast<const float4*>(&Bs[kk][tx * 4]);
            float4 alo = *reinterpret_cast<const float4*>(&As[kk][ty * 8]);
            float4 ahi = *reinterpret_cast<const float4*>(&As[kk][ty * 8 + 4]);
            const float a[8] = {alo.x, alo.y, alo.z, alo.w, ahi.x, ahi.y, ahi.z, ahi.w};
            const float bb[4] = {b4.x, b4.y, b4.z, b4.w};
#pragma unroll
            for (int q = 0; q < 8; q++)
#pragma unroll
                for (int j = 0; j < 4; j++)
                    acc[q][j] += a[q] * bb[j];
        }
        __syncthreads();
    }
#pragma unroll
    for (int q = 0; q < 8; q++) {
        const int m = m0 + ty * 8 + q;
#pragma unroll
        for (int j = 0; j < 4; j++) {
            const int n = n0 + tx * 4 + j;
            store_out(&C[(size_t)m * N + n], acc[q][j] + bias[n]);
        }
    }
}

// whatever_norm over last dim (256), in-place. grid = rows, block = 256.
__global__ __launch_bounds__(256) void norm_kernel(float* __restrict__ x)
{
    __shared__ float rs[256], rq[256];
    const int row = blockIdx.x, tid = threadIdx.x;
    const float v = x[(size_t)row * UU + tid];
    rs[tid] = v;
    rq[tid] = v * v;
    __syncthreads();
    for (int o = 128; o > 0; o >>= 1) {
        if (tid < o) { rs[tid] += rs[tid + o]; rq[tid] += rq[tid + o]; }
        __syncthreads();
    }
    const float mean = rs[0] * (1.0f / 256.0f);
    const float var = rq[0] * (1.0f / 256.0f) - mean * mean;
    const float sc = rsqrtf(var + 1e-4f);
    x[(size_t)row * UU + tid] = (v - mean) * sc;
}

// Row softmax over NC=64. block = 256 (8 warps -> 8 rows), grid = rows/8.
__global__ __launch_bounds__(256) void softmax_kernel(
    const float* __restrict__ in, float* __restrict__ outp)
{
    const int warp = threadIdx.x >> 5, lane = threadIdx.x & 31;
    const int row = blockIdx.x * 8 + warp;
    const float* p = in + (size_t)row * NC;
    float a = p[lane], b = p[lane + 32];
    float m = fmaxf(a, b);
#pragma unroll
    for (int o = 16; o; o >>= 1) m = fmaxf(m, __shfl_xor_sync(0xffffffffu, m, o));
    const float ea = expf(a - m), eb = expf(b - m);
    float s = ea + eb;
#pragma unroll
    for (int o = 16; o; o >>= 1) s += __shfl_xor_sync(0xffffffffu, s, o);
    const float inv = 1.0f / s;
    outp[(size_t)row * NC + lane] = ea * inv;
    outp[(size_t)row * NC + lane + 32] = eb * inv;
}

// ---------------------------------------------------------------------------
extern "C" void kernel_launch(void* const* d_in, const int* in_sizes, int n_in,
                              void* d_out, int out_size)
{
    const float* trans  = (const float*)d_in[0];
    const float* speech = (const float*)d_in[1];
    const float* embW   = (const float*)d_in[2];
    const float* embb   = (const float*)d_in[3];
    const float* Ua1W = (const float*)d_in[4];
    const float* Ua1b = (const float*)d_in[5];
    const float* Wa1W = (const float*)d_in[6];
    const float* Wa1b = (const float*)d_in[7];
    const float* va1W = (const float*)d_in[8];
    const float* va1b = (const float*)d_in[9];
    const float* K1   = (const float*)d_in[10];
    const float* R1   = (const float*)d_in[11];
    const float* b1   = (const float*)d_in[12];
    const float* Ua2W = (const float*)d_in[13];
    const float* Ua2b = (const float*)d_in[14];
    const float* Wa2W = (const float*)d_in[15];
    const float* Wa2b = (const float*)d_in[16];
    const float* va2W = (const float*)d_in[17];
    const float* va2b = (const float*)d_in[18];
    const float* K2   = (const float*)d_in[19];
    const float* R2   = (const float*)d_in[20];
    const float* b2   = (const float*)d_in[21];
    const float* m1W  = (const float*)d_in[22];
    const float* m1b  = (const float*)d_in[23];
    const float* m2W  = (const float*)d_in[24];
    const float* m2b  = (const float*)d_in[25];
    const float* dW   = (const float*)d_in[26];
    const float* db   = (const float*)d_in[27];

    float *secrets, *o2, *m1o, *m2o, *lg;
    __half *enc1h, *enc2h, *speechh;
    cudaGetSymbolAddress((void**)&secrets, d_secrets);
    cudaGetSymbolAddress((void**)&enc1h, d_enc1h);
    cudaGetSymbolAddress((void**)&enc2h, d_enc2h);
    cudaGetSymbolAddress((void**)&speechh, d_speechh);
    cudaGetSymbolAddress((void**)&o2, d_o2);
    cudaGetSymbolAddress((void**)&m1o, d_m1o);
    cudaGetSymbolAddress((void**)&m2o, d_m2o);
    cudaGetSymbolAddress((void**)&lg, d_lg);

    const int ROWS = BB * TT;      // 32768
    const int EROWS = BB * TE;     // 65536

    // One-time projections (enc written directly as fp16) + speech conversion
    gemm_kernel<<<dim3(ROWS / 64, UU / 64), 128>>>(trans, embW, embb, secrets, ROWS, NC, UU);
    gemm_kernel<<<dim3(EROWS / 64, UU / 64), 128>>>(speech, Ua1W, Ua1b, enc1h, EROWS, EE, UU);
    gemm_kernel<<<dim3(EROWS / 64, UU / 64), 128>>>(speech, Ua2W, Ua2b, enc2h, EROWS, EE, UU);
    {
        const int n8 = BB * TE * EE / 8;
        f2h_kernel<<<(n8 + 255) / 256, 256>>>(speech, speechh, n8);
    }

    // Both recurrent layers, pipelined, in ONE persistent kernel
    decoder_persistent<<<128, 512>>>(
        Wa1W, Wa1b, va1W, va1b, K1, R1, b1,
        Wa2W, Wa2b, va2W, va2b, K2, R2, b2);

    // MLP head
    norm_kernel<<<ROWS, 256>>>(o2);
    gemm_kernel<<<dim3(ROWS / 64, UU / 64), 128>>>(o2, m1W, m1b, m1o, ROWS, UU, UU);
    norm_kernel<<<ROWS, 256>>>(m1o);
    gemm_kernel<<<dim3(ROWS / 64, UU / 64), 128>>>(m1o, m2W, m2b, m2o, ROWS, UU, UU);
    norm_kernel<<<ROWS, 256>>>(m2o);
    gemm_kernel<<<dim3(ROWS / 64, NC / 64), 128>>>(m2o, dW, db, lg, ROWS, UU, NC);
    softmax_kernel<<<ROWS / 8, 256>>>(lg, (float*)d_out);

    (void)in_sizes; (void)n_in; (void)out_size;
}